// round 2
// baseline (speedup 1.0000x reference)
#include <cuda_runtime.h>
#include <math.h>

// Problem constants (fixed by the reference)
#define V_SZ 400000
#define S_SZ 4096
#define D_SZ 300
#define C_SZ 4
#define NB   256          // blocks
#define RPB  (S_SZ / NB)  // 16 rows per block
#define NT   320          // threads per block (10 warps)
#define NW   (NT / 32)

// Scratch (device globals; no allocation allowed)
__device__ float g_part1[NB * D_SZ];
__device__ float g_part2[NB * D_SZ];
__device__ float g_mid[D_SZ];
__device__ float g_t[D_SZ];
__device__ float g_scores[S_SZ];
__device__ unsigned g_count = 0;
__device__ unsigned g_sense = 0;

// ---------------------------------------------------------------------------
// Software grid barrier (sense-reversing). Safe: grid of 256 blocks is fully
// resident (launch_bounds(320,4) -> capacity 4*148=592 blocks). Replay-safe:
// g_count returns to 0 every barrier; g_sense just keeps flipping.
// ---------------------------------------------------------------------------
__device__ __forceinline__ void gridbar()
{
    __syncthreads();
    if (threadIdx.x == 0) {
        __threadfence();                                  // release block's writes
        unsigned s = *(volatile unsigned*)&g_sense;
        if (atomicAdd(&g_count, 1u) == NB - 1) {
            g_count = 0;
            __threadfence();
            *(volatile unsigned*)&g_sense = s ^ 1u;       // release
        } else {
            while (*(volatile unsigned*)&g_sense == s) __nanosleep(64);
        }
        __threadfence();                                  // acquire
    }
    __syncthreads();
}

__device__ __forceinline__ float warp_sum(float p) {
    #pragma unroll
    for (int o = 16; o > 0; o >>= 1) p += __shfl_xor_sync(0xFFFFFFFFu, p, o);
    return p;
}
__device__ __forceinline__ float warp_max(float p) {
    #pragma unroll
    for (int o = 16; o > 0; o >>= 1) p = fmaxf(p, __shfl_xor_sync(0xFFFFFFFFu, p, o));
    return p;
}

// Block-wide reductions (fixed order -> deterministic & identical across blocks)
__device__ __forceinline__ float block_sum(float v, float* s_red, int lane, int w) {
    v = warp_sum(v);
    __syncthreads();
    if (lane == 0) s_red[w] = v;
    __syncthreads();
    float r = (lane < NW) ? s_red[lane] : 0.0f;
    return warp_sum(r);
}
__device__ __forceinline__ float block_maxr(float v, float* s_red, int lane, int w) {
    v = warp_max(v);
    __syncthreads();
    if (lane == 0) s_red[w] = v;
    __syncthreads();
    float r = (lane < NW) ? s_red[lane] : -3.4e38f;
    return warp_max(r);
}

// ---------------------------------------------------------------------------
__global__ __launch_bounds__(NT, 4)
void fused_kernel(const int* __restrict__ x, const float* __restrict__ emb,
                  const float* __restrict__ W1, const float* __restrict__ b1,
                  const float* __restrict__ Wb, const float* __restrict__ bb,
                  const float* __restrict__ W2, const float* __restrict__ b2,
                  float* __restrict__ out)
{
    const int b    = blockIdx.x;
    const int tid  = threadIdx.x;
    const int lane = tid & 31;
    const int w    = tid >> 5;

    __shared__ int   s_idx[RPB];
    __shared__ float s_vec[D_SZ];    // dense -> t -> (mid+addition), reused
    __shared__ float s_mid[D_SZ];    // block 0 only, persists phases B..E
    __shared__ float s_red[NW];
    __shared__ float s_w[RPB];
    __shared__ float s_bcast[2];

    if (tid < RPB) s_idx[tid] = x[b * RPB + tid];
    __syncthreads();

    // ---------------- Phase A: gather pass 1 (DRAM), partials [b][d] -------
    if (tid < D_SZ) {
        float a = 0.0f;
        #pragma unroll
        for (int r = 0; r < RPB; r++)
            a += __ldg(&emb[(long)s_idx[r] * D_SZ + tid]);
        g_part1[b * D_SZ + tid] = a;
    }
    gridbar();   // bar 1

    // ---------------- Phase B: block 0 computes dense, mid, t --------------
    if (b == 0) {
        if (tid < D_SZ) {
            float a0 = 0, a1 = 0, a2 = 0, a3 = 0;
            #pragma unroll 4
            for (int q = 0; q < NB; q += 4) {
                a0 += g_part1[(q + 0) * D_SZ + tid];
                a1 += g_part1[(q + 1) * D_SZ + tid];
                a2 += g_part1[(q + 2) * D_SZ + tid];
                a3 += g_part1[(q + 3) * D_SZ + tid];
            }
            s_vec[tid] = ((a0 + a1) + (a2 + a3)) * (1.0f / S_SZ);  // dense
        }
        __syncthreads();
        if (tid < D_SZ) {                                  // mid = W1*dense + b1
            const float* wr = W1 + (long)tid * D_SZ;
            float p0 = 0, p1 = 0, p2 = 0, p3 = 0;
            #pragma unroll 5
            for (int e = 0; e < D_SZ; e += 4) {
                p0 = fmaf(wr[e + 0], s_vec[e + 0], p0);
                p1 = fmaf(wr[e + 1], s_vec[e + 1], p1);
                p2 = fmaf(wr[e + 2], s_vec[e + 2], p2);
                p3 = fmaf(wr[e + 3], s_vec[e + 3], p3);
            }
            float m = ((p0 + p1) + (p2 + p3)) + b1[tid];
            s_mid[tid] = m;
            g_mid[tid] = m;
        }
        __syncthreads();
        if (tid < D_SZ) {                                  // t = Wb*mid
            const float* wr = Wb + (long)tid * D_SZ;
            float p0 = 0, p1 = 0, p2 = 0, p3 = 0;
            #pragma unroll 5
            for (int e = 0; e < D_SZ; e += 4) {
                p0 = fmaf(wr[e + 0], s_mid[e + 0], p0);
                p1 = fmaf(wr[e + 1], s_mid[e + 1], p1);
                p2 = fmaf(wr[e + 2], s_mid[e + 2], p2);
                p3 = fmaf(wr[e + 3], s_mid[e + 3], p3);
            }
            g_t[tid] = ((p0 + p1) + (p2 + p3));
        }
    }
    gridbar();   // bar 2

    // ---------------- Phase C: scores (L2-resident gather, warp-per-row) ---
    if (tid < D_SZ) s_vec[tid] = g_t[tid];
    __syncthreads();
    {
        const float bias = bb[0];
        for (int rr = w; rr < RPB; rr += NW) {
            const float* base = emb + (long)s_idx[rr] * D_SZ;
            float p = 0.0f;
            for (int e = lane; e < D_SZ; e += 32)
                p = fmaf(base[e], s_vec[e], p);
            p = warp_sum(p);
            if (lane == 0) g_scores[b * RPB + rr] = p + bias;
        }
    }
    gridbar();   // bar 3

    // ---------------- Phase D: softmax normalizer (redundant per block) ----
    {
        float mx = -3.4e38f;
        for (int s = tid; s < S_SZ; s += NT) mx = fmaxf(mx, g_scores[s]);
        float bm = block_maxr(mx, s_red, lane, w);
        __syncthreads();
        if (tid == 0) s_bcast[0] = bm;
        __syncthreads();
        bm = s_bcast[0];

        float es = 0.0f;
        for (int s = tid; s < S_SZ; s += NT) es += expf(g_scores[s] - bm);
        float bs = block_sum(es, s_red, lane, w);
        __syncthreads();
        if (tid == 0) s_bcast[1] = bs;
        __syncthreads();
        const float inv = 1.0f / s_bcast[1];

        // block 0 writes the reward output
        if (b == 0)
            for (int s = tid; s < S_SZ; s += NT)
                out[C_SZ + s] = expf(g_scores[s] - bm) * inv;

        // weights for this block's rows
        if (tid < RPB) s_w[tid] = expf(g_scores[b * RPB + tid] - bm) * inv;
        __syncthreads();

        // weighted gather pass (L2-resident)
        if (tid < D_SZ) {
            float a = 0.0f;
            #pragma unroll
            for (int r = 0; r < RPB; r++)
                a = fmaf(s_w[r], __ldg(&emb[(long)s_idx[r] * D_SZ + tid]), a);
            g_part2[b * D_SZ + tid] = a;
        }
    }
    gridbar();   // bar 4

    // ---------------- Phase E: block 0 finalizes output --------------------
    if (b == 0) {
        if (tid < D_SZ) {
            float a0 = 0, a1 = 0, a2 = 0, a3 = 0;
            #pragma unroll 4
            for (int q = 0; q < NB; q += 4) {
                a0 += g_part2[(q + 0) * D_SZ + tid];
                a1 += g_part2[(q + 1) * D_SZ + tid];
                a2 += g_part2[(q + 2) * D_SZ + tid];
                a3 += g_part2[(q + 3) * D_SZ + tid];
            }
            s_vec[tid] = s_mid[tid] + ((a0 + a1) + (a2 + a3)) * (1.0f / S_SZ);
        }
        __syncthreads();
        if (w < C_SZ) {
            float p = 0.0f;
            for (int e = lane; e < D_SZ; e += 32)
                p = fmaf(__ldg(&W2[w * D_SZ + e]), s_vec[e], p);
            p = warp_sum(p);
            if (lane == 0) out[w] = p + b2[w];
        }
    }
}

// ---------------------------------------------------------------------------
extern "C" void kernel_launch(void* const* d_in, const int* in_sizes, int n_in,
                              void* d_out, int out_size)
{
    const int*   x   = (const int*)  d_in[0];
    const float* emb = (const float*)d_in[1];
    const float* W1  = (const float*)d_in[2];
    const float* b1  = (const float*)d_in[3];
    const float* Wb  = (const float*)d_in[4];
    const float* bb  = (const float*)d_in[5];
    const float* W2  = (const float*)d_in[6];
    const float* b2  = (const float*)d_in[7];
    float* out = (float*)d_out;   // out[0:4] = output, out[4:4100] = reward

    fused_kernel<<<NB, NT>>>(x, emb, W1, b1, Wb, bb, W2, b2, out);
}

// round 3
// speedup vs baseline: 1.4947x; 1.4947x over previous
#include <cuda_runtime.h>
#include <math.h>

// Problem constants (fixed by the reference)
#define V_SZ 400000
#define S_SZ 4096
#define D_SZ 300
#define C_SZ 4
#define NB   128            // blocks per kernel
#define RPB  (S_SZ / NB)    // 32 rows per block
#define NT   320            // threads per block (10 warps)
#define NW   (NT / 32)
#define D4   (D_SZ / 4)     // 75 float4 per row

// Scratch (device globals; no allocation allowed)
__device__ float    g_part1[NB * D_SZ];
__device__ float    g_part2[NB * D_SZ];
__device__ float    g_mid[D_SZ];
__device__ float    g_t[D_SZ];
__device__ float    g_scores[S_SZ];
__device__ float    g_reward[S_SZ];
__device__ unsigned g_cnt1 = 0, g_cnt2 = 0, g_cnt3 = 0;

__device__ __forceinline__ float warp_sum(float p) {
    #pragma unroll
    for (int o = 16; o > 0; o >>= 1) p += __shfl_xor_sync(0xFFFFFFFFu, p, o);
    return p;
}
__device__ __forceinline__ float warp_max(float p) {
    #pragma unroll
    for (int o = 16; o > 0; o >>= 1) p = fmaxf(p, __shfl_xor_sync(0xFFFFFFFFu, p, o));
    return p;
}

// Last-block-done: returns true in exactly one block after all NB blocks'
// global stores are visible. Counter self-resets -> graph-replay safe.
__device__ __forceinline__ bool last_block(unsigned* cnt, bool* s_last) {
    __threadfence();                       // release this block's stores
    __syncthreads();
    if (threadIdx.x == 0)
        *s_last = (atomicAdd(cnt, 1u) == NB - 1);
    __syncthreads();
    if (*s_last) {
        __threadfence();                   // acquire other blocks' stores
        if (threadIdx.x == 0) *cnt = 0;    // reset for next replay
        return true;
    }
    return false;
}

// Deterministic reduce of NB partials per dim (coalesced: consecutive tid ->
// consecutive d within each block's row).
__device__ __forceinline__ float reduce_parts(const float* part, int d) {
    float a0 = 0, a1 = 0, a2 = 0, a3 = 0;
    #pragma unroll 8
    for (int q = 0; q < NB; q += 4) {
        a0 += part[(q + 0) * D_SZ + d];
        a1 += part[(q + 1) * D_SZ + d];
        a2 += part[(q + 2) * D_SZ + d];
        a3 += part[(q + 3) * D_SZ + d];
    }
    return (a0 + a1) + (a2 + a3);
}

// Row-per-thread matvec with float4 loads: y[d] = W[d,:] . v  (v in smem)
__device__ __forceinline__ float matvec_row(const float* W, const float4* v4, int d) {
    const float4* wr = (const float4*)(W + (long)d * D_SZ);
    float p0 = 0, p1 = 0, p2 = 0, p3 = 0;
    #pragma unroll 5
    for (int i = 0; i < D4; i++) {
        float4 w = wr[i];
        float4 v = v4[i];
        p0 = fmaf(w.x, v.x, p0);
        p1 = fmaf(w.y, v.y, p1);
        p2 = fmaf(w.z, v.z, p2);
        p3 = fmaf(w.w, v.w, p3);
    }
    return (p0 + p1) + (p2 + p3);
}

// ---------------------------------------------------------------------------
// K_A: gather partials; last block -> dense, mid = W1*dense+b1, t = Wb*mid
// ---------------------------------------------------------------------------
__global__ __launch_bounds__(NT)
void k_gather_mlp(const int* __restrict__ x, const float* __restrict__ emb,
                  const float* __restrict__ W1, const float* __restrict__ b1,
                  const float* __restrict__ Wb)
{
    __shared__ int    s_idx[RPB];
    __shared__ bool   s_last;
    __shared__ float4 s_vec4[D4];
    __shared__ float4 s_mid4[D4];
    float* s_vec = (float*)s_vec4;
    float* s_mid = (float*)s_mid4;

    const int b = blockIdx.x, tid = threadIdx.x;

    if (tid < RPB) s_idx[tid] = x[b * RPB + tid];
    __syncthreads();

    if (tid < D_SZ) {
        float a = 0.0f;
        #pragma unroll 8
        for (int r = 0; r < RPB; r++)
            a += __ldg(&emb[(long)s_idx[r] * D_SZ + tid]);
        g_part1[b * D_SZ + tid] = a;
    }

    if (!last_block(&g_cnt1, &s_last)) return;

    // ---- tail: dense = reduce/S ----
    if (tid < D_SZ) s_vec[tid] = reduce_parts(g_part1, tid) * (1.0f / S_SZ);
    __syncthreads();
    // ---- mid = W1*dense + b1 ----
    if (tid < D_SZ) s_mid[tid] = matvec_row(W1, s_vec4, tid) + b1[tid];
    __syncthreads();
    if (tid < D_SZ) g_mid[tid] = s_mid[tid];
    // ---- t = Wb*mid ----
    if (tid < D_SZ) g_t[tid] = matvec_row(Wb, s_mid4, tid);
}

// ---------------------------------------------------------------------------
// K_B: scores (warp-per-row, L2-resident); last block -> softmax + reward
// ---------------------------------------------------------------------------
__global__ __launch_bounds__(NT)
void k_scores_softmax(const int* __restrict__ x, const float* __restrict__ emb,
                      const float* __restrict__ bb, float* __restrict__ reward_out)
{
    __shared__ float s_t[D_SZ];
    __shared__ bool  s_last;
    __shared__ float s_red[NW];
    __shared__ float s_bc;

    const int tid = threadIdx.x, lane = tid & 31, w = tid >> 5;

    if (tid < D_SZ) s_t[tid] = g_t[tid];
    __syncthreads();

    const float bias = bb[0];
    const int gw = (blockIdx.x * NT + tid) >> 5;
    const int ngw = (NB * NT) >> 5;            // 1280 warps
    for (int s = gw; s < S_SZ; s += ngw) {
        const float* base = emb + (long)__ldg(&x[s]) * D_SZ;
        float p = 0.0f;
        #pragma unroll 10
        for (int e = lane; e < D_SZ; e += 32) p = fmaf(base[e], s_t[e], p);
        p = warp_sum(p);
        if (lane == 0) g_scores[s] = p + bias;
    }

    if (!last_block(&g_cnt2, &s_last)) return;

    // ---- tail: softmax over 4096 scores (fixed order) ----
    float mx = -3.4e38f;
    for (int s = tid; s < S_SZ; s += NT) mx = fmaxf(mx, g_scores[s]);
    mx = warp_max(mx);
    if (lane == 0) s_red[w] = mx;
    __syncthreads();
    float bm = (lane < NW) ? s_red[lane] : -3.4e38f;
    bm = warp_max(bm);
    if (tid == 0) s_bc = bm;
    __syncthreads();
    bm = s_bc;

    float es = 0.0f;
    for (int s = tid; s < S_SZ; s += NT) es += expf(g_scores[s] - bm);
    es = warp_sum(es);
    __syncthreads();
    if (lane == 0) s_red[w] = es;
    __syncthreads();
    float bs = (lane < NW) ? s_red[lane] : 0.0f;
    bs = warp_sum(bs);
    if (tid == 0) s_bc = 1.0f / bs;
    __syncthreads();
    const float inv = s_bc;

    for (int s = tid; s < S_SZ; s += NT) {
        float r = expf(g_scores[s] - bm) * inv;
        reward_out[s] = r;
        g_reward[s]   = r;
    }
}

// ---------------------------------------------------------------------------
// K_C: weighted gather (L2-resident); last block -> addition, output logits
// ---------------------------------------------------------------------------
__global__ __launch_bounds__(NT)
void k_weighted_final(const int* __restrict__ x, const float* __restrict__ emb,
                      const float* __restrict__ W2, const float* __restrict__ b2,
                      float* __restrict__ out)
{
    __shared__ int   s_idx[RPB];
    __shared__ float s_w[RPB];
    __shared__ bool  s_last;
    __shared__ float s_vec[D_SZ];

    const int b = blockIdx.x, tid = threadIdx.x, lane = tid & 31, w = tid >> 5;

    if (tid < RPB) {
        s_idx[tid] = x[b * RPB + tid];
        s_w[tid]   = g_reward[b * RPB + tid];
    }
    __syncthreads();

    if (tid < D_SZ) {
        float a = 0.0f;
        #pragma unroll 8
        for (int r = 0; r < RPB; r++)
            a = fmaf(s_w[r], __ldg(&emb[(long)s_idx[r] * D_SZ + tid]), a);
        g_part2[b * D_SZ + tid] = a;
    }

    if (!last_block(&g_cnt3, &s_last)) return;

    // ---- tail: addition + mid, then 4 output dots ----
    if (tid < D_SZ)
        s_vec[tid] = g_mid[tid] + reduce_parts(g_part2, tid) * (1.0f / S_SZ);
    __syncthreads();

    if (w < C_SZ) {
        const float* wr = W2 + (long)w * D_SZ;
        float p = 0.0f;
        #pragma unroll 10
        for (int e = lane; e < D_SZ; e += 32) p = fmaf(__ldg(&wr[e]), s_vec[e], p);
        p = warp_sum(p);
        if (lane == 0) out[w] = p + b2[w];
    }
}

// ---------------------------------------------------------------------------
extern "C" void kernel_launch(void* const* d_in, const int* in_sizes, int n_in,
                              void* d_out, int out_size)
{
    const int*   x   = (const int*)  d_in[0];
    const float* emb = (const float*)d_in[1];
    const float* W1  = (const float*)d_in[2];
    const float* b1  = (const float*)d_in[3];
    const float* Wb  = (const float*)d_in[4];
    const float* bb  = (const float*)d_in[5];
    const float* W2  = (const float*)d_in[6];
    const float* b2  = (const float*)d_in[7];
    float* out = (float*)d_out;   // out[0:4] = output, out[4:4100] = reward

    k_gather_mlp<<<NB, NT>>>(x, emb, W1, b1, Wb);
    k_scores_softmax<<<NB, NT>>>(x, emb, bb, out + C_SZ);
    k_weighted_final<<<NB, NT>>>(x, emb, W2, b2, out);
}